// round 1
// baseline (speedup 1.0000x reference)
#include <cuda_runtime.h>
#include <cuda_bf16.h>
#include <math.h>

// Problem constants (fixed shapes from reference)
#define BATCH 4
#define SEQ   2048
#define DIM   1024
#define NHEAD 16
#define HDIM  64
#define QKVN  (3 * DIM)   // 3072

// Scratch buffers (device globals — no allocation allowed)
__device__ float g_qkv[(size_t)BATCH * SEQ * QKVN];  // [B*T, 3072]
__device__ float g_y[(size_t)BATCH * SEQ * DIM];     // [B*T, 1024] attention output

// ---------------------------------------------------------------------------
// Generic SGEMM with fused bias: C[M,N] = A[M,K] @ B[K,N] + bias[N]
// BM=BN=128, BK=16, 256 threads, 8x8 per thread.
// Requires M%128==0, N%128==0, K%16==0 (true for all our shapes).
// ---------------------------------------------------------------------------
__global__ __launch_bounds__(256) void sgemm_bias_kernel(
    const float* __restrict__ A, const float* __restrict__ B,
    const float* __restrict__ bias, float* __restrict__ C,
    int M, int N, int K)
{
    __shared__ float As[16][128];
    __shared__ float Bs[16][128];

    const int tid  = threadIdx.x;
    const int row0 = blockIdx.y * 128;
    const int col0 = blockIdx.x * 128;
    const int tx = tid & 15;     // 0..15 -> N
    const int ty = tid >> 4;     // 0..15 -> M

    const int a_r = tid >> 2;          // 0..63
    const int a_c = (tid & 3) * 4;     // 0,4,8,12
    const int b_r = tid >> 5;          // 0..7
    const int b_c = (tid & 31) * 4;    // 0..124

    float acc[8][8];
#pragma unroll
    for (int i = 0; i < 8; i++)
#pragma unroll
        for (int j = 0; j < 8; j++) acc[i][j] = 0.f;

    for (int k0 = 0; k0 < K; k0 += 16) {
        // Load A tile (128 x 16), store transposed As[k][m]
#pragma unroll
        for (int rr = 0; rr < 2; rr++) {
            int r = a_r + rr * 64;
            float4 v = *(const float4*)&A[(size_t)(row0 + r) * K + k0 + a_c];
            As[a_c + 0][r] = v.x;
            As[a_c + 1][r] = v.y;
            As[a_c + 2][r] = v.z;
            As[a_c + 3][r] = v.w;
        }
        // Load B tile (16 x 128)
#pragma unroll
        for (int rr = 0; rr < 2; rr++) {
            int r = b_r + rr * 8;
            *(float4*)&Bs[r][b_c] =
                *(const float4*)&B[(size_t)(k0 + r) * N + col0 + b_c];
        }
        __syncthreads();

#pragma unroll
        for (int k = 0; k < 16; k++) {
            float am[8], bn[8];
            *(float4*)&am[0] = *(float4*)&As[k][ty * 8];
            *(float4*)&am[4] = *(float4*)&As[k][ty * 8 + 4];
            *(float4*)&bn[0] = *(float4*)&Bs[k][tx * 8];
            *(float4*)&bn[4] = *(float4*)&Bs[k][tx * 8 + 4];
#pragma unroll
            for (int i = 0; i < 8; i++)
#pragma unroll
                for (int j = 0; j < 8; j++)
                    acc[i][j] += am[i] * bn[j];
        }
        __syncthreads();
    }

    // Epilogue: add bias, vectorized store
#pragma unroll
    for (int i = 0; i < 8; i++) {
        int r = row0 + ty * 8 + i;
#pragma unroll
        for (int j4 = 0; j4 < 2; j4++) {
            int c = col0 + tx * 8 + j4 * 4;
            float4 bv = *(const float4*)&bias[c];
            float4 o;
            o.x = acc[i][j4 * 4 + 0] + bv.x;
            o.y = acc[i][j4 * 4 + 1] + bv.y;
            o.z = acc[i][j4 * 4 + 2] + bv.z;
            o.w = acc[i][j4 * 4 + 3] + bv.w;
            *(float4*)&C[(size_t)r * N + c] = o;
        }
    }
}

// ---------------------------------------------------------------------------
// Flash-attention (fp32, causal). One CTA = one (b, h, 64-query tile).
// 256 threads: thread t owns query row r = t/4, dims [ (t%4)*16, +16 ).
// Online softmax with shuffle reductions across the 4 threads of a row.
// K/V tiles streamed through smem; tiles past the diagonal are skipped.
// ---------------------------------------------------------------------------
#define SSTR 68   // smem row stride: 68%4==0 (16B-aligned float4) and shifts banks

__global__ __launch_bounds__(256) void attn_kernel(
    const float* __restrict__ qkv, float* __restrict__ y)
{
    extern __shared__ float sm[];
    float* Qs = sm;                    // 64 x SSTR
    float* Ks = sm + 64 * SSTR;
    float* Vs = sm + 2 * 64 * SSTR;
    float* Ps = sm + 3 * 64 * SSTR;

    const int bx  = blockIdx.x;        // query tile index (0..31)
    const int h   = blockIdx.y;        // head
    const int b   = blockIdx.z;        // batch
    const int tid = threadIdx.x;
    const int q0  = bx * 64;

    const size_t base = (size_t)b * SEQ * QKVN;

    // Load Q tile, pre-scaled by 1/sqrt(hd) = 0.125
    {
        int lr = tid >> 4;             // 0..15
        int c4 = (tid & 15) * 4;       // 0..60
#pragma unroll
        for (int p = 0; p < 4; p++) {
            int rr = lr + p * 16;
            float4 v = *(const float4*)&qkv[base + (size_t)(q0 + rr) * QKVN + h * HDIM + c4];
            float4 s;
            s.x = v.x * 0.125f; s.y = v.y * 0.125f;
            s.z = v.z * 0.125f; s.w = v.w * 0.125f;
            *(float4*)&Qs[rr * SSTR + c4] = s;
        }
    }

    const int r    = tid >> 2;         // query row within tile, 0..63
    const int quad = tid & 3;
    const int cb   = quad * 16;        // this thread's column/dim base

    float m_i = -INFINITY;
    float l_i = 0.f;
    float O[16];
#pragma unroll
    for (int j = 0; j < 16; j++) O[j] = 0.f;

    for (int kt = 0; kt <= bx; kt++) {
        const int k0 = kt * 64;
        __syncthreads();  // previous iteration's Ps/Vs reads done; Q load done (first iter)

        // Load K and V tiles
        {
            int lr = tid >> 4;
            int c4 = (tid & 15) * 4;
#pragma unroll
            for (int p = 0; p < 4; p++) {
                int rr = lr + p * 16;
                size_t g = base + (size_t)(k0 + rr) * QKVN + h * HDIM + c4;
                *(float4*)&Ks[rr * SSTR + c4] = *(const float4*)&qkv[g + DIM];
                *(float4*)&Vs[rr * SSTR + c4] = *(const float4*)&qkv[g + 2 * DIM];
            }
        }
        __syncthreads();

        // S = Q K^T  (this thread: row r, cols cb..cb+15)
        float s[16];
#pragma unroll
        for (int j = 0; j < 16; j++) s[j] = 0.f;
#pragma unroll 4
        for (int kk = 0; kk < HDIM; kk += 4) {
            float4 q = *(float4*)&Qs[r * SSTR + kk];
#pragma unroll
            for (int j = 0; j < 16; j++) {
                float4 kv = *(float4*)&Ks[(cb + j) * SSTR + kk];
                s[j] += q.x * kv.x + q.y * kv.y + q.z * kv.z + q.w * kv.w;
            }
        }

        // Causal mask (only on the diagonal tile; earlier tiles fully visible)
        if (kt == bx) {
#pragma unroll
            for (int j = 0; j < 16; j++)
                if (cb + j > r) s[j] = -INFINITY;
        }

        // Row max across this thread's 16 cols, then across the 4-thread quad group
        float mt = s[0];
#pragma unroll
        for (int j = 1; j < 16; j++) mt = fmaxf(mt, s[j]);
        mt = fmaxf(mt, __shfl_xor_sync(0xffffffffu, mt, 1));
        mt = fmaxf(mt, __shfl_xor_sync(0xffffffffu, mt, 2));

        float m_new = fmaxf(m_i, mt);
        float corr  = __expf(m_i - m_new);   // 0 when m_i == -inf

        float ssum = 0.f;
#pragma unroll
        for (int j = 0; j < 16; j++) {
            float p = __expf(s[j] - m_new);  // exp(-inf) -> 0 for masked
            s[j] = p;
            ssum += p;
        }
        ssum += __shfl_xor_sync(0xffffffffu, ssum, 1);
        ssum += __shfl_xor_sync(0xffffffffu, ssum, 2);

        l_i = l_i * corr + ssum;
        m_i = m_new;
#pragma unroll
        for (int j = 0; j < 16; j++) O[j] *= corr;

        // Publish P row-chunk to smem for the PV product
#pragma unroll
        for (int j4 = 0; j4 < 4; j4++) {
            float4 p4;
            p4.x = s[j4 * 4 + 0]; p4.y = s[j4 * 4 + 1];
            p4.z = s[j4 * 4 + 2]; p4.w = s[j4 * 4 + 3];
            *(float4*)&Ps[r * SSTR + cb + j4 * 4] = p4;
        }
        __syncthreads();

        // O += P @ V   (this thread: row r, dims cb..cb+15)
#pragma unroll 4
        for (int c = 0; c < 64; c++) {
            float p = Ps[r * SSTR + c];
#pragma unroll
            for (int j4 = 0; j4 < 4; j4++) {
                float4 v = *(float4*)&Vs[c * SSTR + cb + j4 * 4];
                O[j4 * 4 + 0] += p * v.x;
                O[j4 * 4 + 1] += p * v.y;
                O[j4 * 4 + 2] += p * v.z;
                O[j4 * 4 + 3] += p * v.w;
            }
        }
    }

    // Normalize and write y[b, q0+r, h*64 + cb .. +16]
    const float inv = 1.f / l_i;
    const size_t yb = ((size_t)b * SEQ + q0 + r) * DIM + h * HDIM + cb;
#pragma unroll
    for (int j4 = 0; j4 < 4; j4++) {
        float4 o;
        o.x = O[j4 * 4 + 0] * inv;
        o.y = O[j4 * 4 + 1] * inv;
        o.z = O[j4 * 4 + 2] * inv;
        o.w = O[j4 * 4 + 3] * inv;
        *(float4*)&y[yb + j4 * 4] = o;
    }
}

// ---------------------------------------------------------------------------
// Launch
// ---------------------------------------------------------------------------
extern "C" void kernel_launch(void* const* d_in, const int* in_sizes, int n_in,
                              void* d_out, int out_size)
{
    const float* x      = (const float*)d_in[0];   // [B,T,D]
    const float* W_attn = (const float*)d_in[1];   // [D, 3D]
    const float* b_attn = (const float*)d_in[2];   // [3D]
    const float* W_proj = (const float*)d_in[3];   // [D, D]
    const float* b_proj = (const float*)d_in[4];   // [D]
    float* out = (float*)d_out;                    // [B,T,D]

    void* qkv_p = nullptr;
    void* y_p   = nullptr;
    cudaGetSymbolAddress(&qkv_p, g_qkv);
    cudaGetSymbolAddress(&y_p, g_y);
    float* qkv = (float*)qkv_p;
    float* y   = (float*)y_p;

    const int M = BATCH * SEQ;  // 8192

    // 1) QKV projection: [8192,1024] @ [1024,3072] + bias
    {
        dim3 grid(QKVN / 128, M / 128);
        sgemm_bias_kernel<<<grid, 256>>>(x, W_attn, b_attn, qkv, M, QKVN, DIM);
    }

    // 2) Causal flash attention
    {
        const int smem = 4 * 64 * SSTR * (int)sizeof(float);  // 69632 B
        cudaFuncSetAttribute(attn_kernel, cudaFuncAttributeMaxDynamicSharedMemorySize, smem);
        dim3 grid(SEQ / 64, NHEAD, BATCH);
        attn_kernel<<<grid, 256, smem>>>(qkv, y);
    }

    // 3) Output projection: [8192,1024] @ [1024,1024] + bias
    {
        dim3 grid(DIM / 128, M / 128);
        sgemm_bias_kernel<<<grid, 256>>>(y, W_proj, b_proj, out, M, DIM, DIM);
    }
}

// round 2
// speedup vs baseline: 1.0652x; 1.0652x over previous
#include <cuda_runtime.h>
#include <cuda_bf16.h>
#include <math.h>

// Problem constants (fixed shapes from reference)
#define BATCH 4
#define SEQ   2048
#define DIM   1024
#define NHEAD 16
#define HDIM  64
#define QKVN  (3 * DIM)   // 3072

// Scratch buffers (device globals — no allocation allowed)
__device__ float g_qkv[(size_t)BATCH * SEQ * QKVN];  // [B*T, 3072]
__device__ float g_y[(size_t)BATCH * SEQ * DIM];     // [B*T, 1024] attention output

// ---------------------------------------------------------------------------
// TF32 tensor-core GEMM with fused bias: C[M,N] = A[M,K] @ B[K,N] + bias[N]
// BM=BN=128, BK=32, 256 threads (8 warps in 4x2 grid), mma.sync m16n8k8 tf32.
// Requires M%128==0, N%128==0, K%32==0.
// ---------------------------------------------------------------------------
#define ASTR 133   // As row stride (k-major: As[k][m]) — conflict-free scalar STS
#define BSTR 132   // Bs row stride (Bs[k][n]) — 16B-aligned float4 STS

__device__ __forceinline__ unsigned f2tf32(float x) {
    unsigned u;
    asm("cvt.rna.tf32.f32 %0, %1;" : "=r"(u) : "f"(x));
    return u;
}

__device__ __forceinline__ void mma_tf32(float c[4], const unsigned a[4], const unsigned b[2]) {
    asm volatile(
        "mma.sync.aligned.m16n8k8.row.col.f32.tf32.tf32.f32 "
        "{%0,%1,%2,%3}, {%4,%5,%6,%7}, {%8,%9}, {%0,%1,%2,%3};\n"
        : "+f"(c[0]), "+f"(c[1]), "+f"(c[2]), "+f"(c[3])
        : "r"(a[0]), "r"(a[1]), "r"(a[2]), "r"(a[3]),
          "r"(b[0]), "r"(b[1]));
}

__global__ __launch_bounds__(256) void gemm_tf32_bias_kernel(
    const float* __restrict__ A, const float* __restrict__ B,
    const float* __restrict__ bias, float* __restrict__ C,
    int M, int N, int K)
{
    __shared__ float As[32 * ASTR];   // tf32 bit patterns, [k][m]
    __shared__ float Bs[32 * BSTR];   // tf32 bit patterns, [k][n]

    const int tid  = threadIdx.x;
    const int row0 = blockIdx.y * 128;
    const int col0 = blockIdx.x * 128;

    const int wid = tid >> 5;
    const int lid = tid & 31;
    const int wm  = wid & 3;          // 0..3 -> m offset wm*32
    const int wn  = wid >> 2;         // 0..1 -> n offset wn*64
    const int g   = lid >> 2;         // group id 0..7
    const int t   = lid & 3;          // thread-in-group 0..3

    // Global load assignment
    const int a_r  = tid >> 1;              // 0..127 (m row)
    const int a_c0 = (tid & 1) * 16;        // 0 or 16 (k col base)
    const int b_r  = tid >> 3;              // 0..31  (k row)
    const int b_c0 = (tid & 7) * 16;        // n col base

    const float* Aptr = A + (size_t)(row0 + a_r) * K + a_c0;
    const float* Bptr = B + (size_t)b_r * N + col0 + b_c0;

    float c_[2][8][4];
#pragma unroll
    for (int mt = 0; mt < 2; mt++)
#pragma unroll
        for (int nt = 0; nt < 8; nt++)
#pragma unroll
            for (int i = 0; i < 4; i++) c_[mt][nt][i] = 0.f;

    float4 ar[4], br[4];

    // Prologue: load first tile
#pragma unroll
    for (int j = 0; j < 4; j++) {
        ar[j] = *(const float4*)(Aptr + j * 4);
        br[j] = *(const float4*)(Bptr + j * 4);
    }

    const int KITER = K / 32;
    for (int it = 0; it < KITER; it++) {
        // Store current tile to smem (with tf32 rounding)
#pragma unroll
        for (int j = 0; j < 4; j++) {
            // A transposed scalar stores: As[k][m]
            As[(a_c0 + j * 4 + 0) * ASTR + a_r] = __uint_as_float(f2tf32(ar[j].x));
            As[(a_c0 + j * 4 + 1) * ASTR + a_r] = __uint_as_float(f2tf32(ar[j].y));
            As[(a_c0 + j * 4 + 2) * ASTR + a_r] = __uint_as_float(f2tf32(ar[j].z));
            As[(a_c0 + j * 4 + 3) * ASTR + a_r] = __uint_as_float(f2tf32(ar[j].w));
            // B natural float4 store
            float4 bv;
            bv.x = __uint_as_float(f2tf32(br[j].x));
            bv.y = __uint_as_float(f2tf32(br[j].y));
            bv.z = __uint_as_float(f2tf32(br[j].z));
            bv.w = __uint_as_float(f2tf32(br[j].w));
            *(float4*)&Bs[b_r * BSTR + b_c0 + j * 4] = bv;
        }
        __syncthreads();

        // Prefetch next tile into registers
        if (it + 1 < KITER) {
            const float* An = Aptr + (it + 1) * 32;
            const float* Bn = Bptr + (size_t)(it + 1) * 32 * N;
#pragma unroll
            for (int j = 0; j < 4; j++) {
                ar[j] = *(const float4*)(An + j * 4);
                br[j] = *(const float4*)(Bn + j * 4);
            }
        }

        // Compute: 4 k-steps of m16n8k8
#pragma unroll
        for (int ks = 0; ks < 4; ks++) {
            const int ko = ks * 8;
            unsigned a_[2][4], b_[8][2];
#pragma unroll
            for (int mt = 0; mt < 2; mt++) {
                const int mo = wm * 32 + mt * 16;
                a_[mt][0] = __float_as_uint(As[(ko + t)     * ASTR + mo + g]);
                a_[mt][1] = __float_as_uint(As[(ko + t)     * ASTR + mo + g + 8]);
                a_[mt][2] = __float_as_uint(As[(ko + t + 4) * ASTR + mo + g]);
                a_[mt][3] = __float_as_uint(As[(ko + t + 4) * ASTR + mo + g + 8]);
            }
#pragma unroll
            for (int nt = 0; nt < 8; nt++) {
                const int no = wn * 64 + nt * 8;
                b_[nt][0] = __float_as_uint(Bs[(ko + t)     * BSTR + no + g]);
                b_[nt][1] = __float_as_uint(Bs[(ko + t + 4) * BSTR + no + g]);
            }
#pragma unroll
            for (int mt = 0; mt < 2; mt++)
#pragma unroll
                for (int nt = 0; nt < 8; nt++)
                    mma_tf32(c_[mt][nt], a_[mt], b_[nt]);
        }
        __syncthreads();
    }

    // Epilogue: bias + store (c0,c1 adjacent cols -> float2)
#pragma unroll
    for (int mt = 0; mt < 2; mt++) {
        const int r0 = row0 + wm * 32 + mt * 16 + g;
#pragma unroll
        for (int nt = 0; nt < 8; nt++) {
            const int c = col0 + wn * 64 + nt * 8 + 2 * t;
            const float b0 = __ldg(&bias[c]);
            const float b1 = __ldg(&bias[c + 1]);
            float2 v0, v1;
            v0.x = c_[mt][nt][0] + b0;
            v0.y = c_[mt][nt][1] + b1;
            v1.x = c_[mt][nt][2] + b0;
            v1.y = c_[mt][nt][3] + b1;
            *(float2*)&C[(size_t)r0 * N + c]       = v0;
            *(float2*)&C[(size_t)(r0 + 8) * N + c] = v1;
        }
    }
}

// ---------------------------------------------------------------------------
// Flash-attention (fp32, causal). One CTA = one (b, h, 64-query tile).
// 256 threads: thread t owns query row r = t/4, dims [ (t%4)*16, +16 ).
// Online softmax with shuffle reductions across the 4 threads of a row.
// K/V tiles streamed through smem; tiles past the diagonal are skipped.
// ---------------------------------------------------------------------------
#define SSTR 68   // smem row stride: 68%4==0 (16B-aligned float4) and shifts banks

__global__ __launch_bounds__(256) void attn_kernel(
    const float* __restrict__ qkv, float* __restrict__ y)
{
    extern __shared__ float sm[];
    float* Qs = sm;                    // 64 x SSTR
    float* Ks = sm + 64 * SSTR;
    float* Vs = sm + 2 * 64 * SSTR;
    float* Ps = sm + 3 * 64 * SSTR;

    const int bx  = blockIdx.x;        // query tile index (0..31)
    const int h   = blockIdx.y;        // head
    const int b   = blockIdx.z;        // batch
    const int tid = threadIdx.x;
    const int q0  = bx * 64;

    const size_t base = (size_t)b * SEQ * QKVN;

    // Load Q tile, pre-scaled by 1/sqrt(hd) = 0.125
    {
        int lr = tid >> 4;             // 0..15
        int c4 = (tid & 15) * 4;       // 0..60
#pragma unroll
        for (int p = 0; p < 4; p++) {
            int rr = lr + p * 16;
            float4 v = *(const float4*)&qkv[base + (size_t)(q0 + rr) * QKVN + h * HDIM + c4];
            float4 s;
            s.x = v.x * 0.125f; s.y = v.y * 0.125f;
            s.z = v.z * 0.125f; s.w = v.w * 0.125f;
            *(float4*)&Qs[rr * SSTR + c4] = s;
        }
    }

    const int r    = tid >> 2;         // query row within tile, 0..63
    const int quad = tid & 3;
    const int cb   = quad * 16;        // this thread's column/dim base

    float m_i = -INFINITY;
    float l_i = 0.f;
    float O[16];
#pragma unroll
    for (int j = 0; j < 16; j++) O[j] = 0.f;

    for (int kt = 0; kt <= bx; kt++) {
        const int k0 = kt * 64;
        __syncthreads();  // previous iteration's Ps/Vs reads done; Q load done (first iter)

        // Load K and V tiles
        {
            int lr = tid >> 4;
            int c4 = (tid & 15) * 4;
#pragma unroll
            for (int p = 0; p < 4; p++) {
                int rr = lr + p * 16;
                size_t gg = base + (size_t)(k0 + rr) * QKVN + h * HDIM + c4;
                *(float4*)&Ks[rr * SSTR + c4] = *(const float4*)&qkv[gg + DIM];
                *(float4*)&Vs[rr * SSTR + c4] = *(const float4*)&qkv[gg + 2 * DIM];
            }
        }
        __syncthreads();

        // S = Q K^T  (this thread: row r, cols cb..cb+15)
        float s[16];
#pragma unroll
        for (int j = 0; j < 16; j++) s[j] = 0.f;
#pragma unroll 4
        for (int kk = 0; kk < HDIM; kk += 4) {
            float4 q = *(float4*)&Qs[r * SSTR + kk];
#pragma unroll
            for (int j = 0; j < 16; j++) {
                float4 kv = *(float4*)&Ks[(cb + j) * SSTR + kk];
                s[j] += q.x * kv.x + q.y * kv.y + q.z * kv.z + q.w * kv.w;
            }
        }

        // Causal mask (only on the diagonal tile; earlier tiles fully visible)
        if (kt == bx) {
#pragma unroll
            for (int j = 0; j < 16; j++)
                if (cb + j > r) s[j] = -INFINITY;
        }

        // Row max across this thread's 16 cols, then across the 4-thread quad group
        float mt = s[0];
#pragma unroll
        for (int j = 1; j < 16; j++) mt = fmaxf(mt, s[j]);
        mt = fmaxf(mt, __shfl_xor_sync(0xffffffffu, mt, 1));
        mt = fmaxf(mt, __shfl_xor_sync(0xffffffffu, mt, 2));

        float m_new = fmaxf(m_i, mt);
        float corr  = __expf(m_i - m_new);   // 0 when m_i == -inf

        float ssum = 0.f;
#pragma unroll
        for (int j = 0; j < 16; j++) {
            float p = __expf(s[j] - m_new);  // exp(-inf) -> 0 for masked
            s[j] = p;
            ssum += p;
        }
        ssum += __shfl_xor_sync(0xffffffffu, ssum, 1);
        ssum += __shfl_xor_sync(0xffffffffu, ssum, 2);

        l_i = l_i * corr + ssum;
        m_i = m_new;
#pragma unroll
        for (int j = 0; j < 16; j++) O[j] *= corr;

        // Publish P row-chunk to smem for the PV product
#pragma unroll
        for (int j4 = 0; j4 < 4; j4++) {
            float4 p4;
            p4.x = s[j4 * 4 + 0]; p4.y = s[j4 * 4 + 1];
            p4.z = s[j4 * 4 + 2]; p4.w = s[j4 * 4 + 3];
            *(float4*)&Ps[r * SSTR + cb + j4 * 4] = p4;
        }
        __syncthreads();

        // O += P @ V   (this thread: row r, dims cb..cb+15)
#pragma unroll 4
        for (int c = 0; c < 64; c++) {
            float p = Ps[r * SSTR + c];
#pragma unroll
            for (int j4 = 0; j4 < 4; j4++) {
                float4 v = *(float4*)&Vs[c * SSTR + cb + j4 * 4];
                O[j4 * 4 + 0] += p * v.x;
                O[j4 * 4 + 1] += p * v.y;
                O[j4 * 4 + 2] += p * v.z;
                O[j4 * 4 + 3] += p * v.w;
            }
        }
    }

    // Normalize and write y[b, q0+r, h*64 + cb .. +16]
    const float inv = 1.f / l_i;
    const size_t yb = ((size_t)b * SEQ + q0 + r) * DIM + h * HDIM + cb;
#pragma unroll
    for (int j4 = 0; j4 < 4; j4++) {
        float4 o;
        o.x = O[j4 * 4 + 0] * inv;
        o.y = O[j4 * 4 + 1] * inv;
        o.z = O[j4 * 4 + 2] * inv;
        o.w = O[j4 * 4 + 3] * inv;
        *(float4*)&y[yb + j4 * 4] = o;
    }
}

// ---------------------------------------------------------------------------
// Launch
// ---------------------------------------------------------------------------
extern "C" void kernel_launch(void* const* d_in, const int* in_sizes, int n_in,
                              void* d_out, int out_size)
{
    const float* x      = (const float*)d_in[0];   // [B,T,D]
    const float* W_attn = (const float*)d_in[1];   // [D, 3D]
    const float* b_attn = (const float*)d_in[2];   // [3D]
    const float* W_proj = (const float*)d_in[3];   // [D, D]
    const float* b_proj = (const float*)d_in[4];   // [D]
    float* out = (float*)d_out;                    // [B,T,D]

    void* qkv_p = nullptr;
    void* y_p   = nullptr;
    cudaGetSymbolAddress(&qkv_p, g_qkv);
    cudaGetSymbolAddress(&y_p, g_y);
    float* qkv = (float*)qkv_p;
    float* y   = (float*)y_p;

    const int M = BATCH * SEQ;  // 8192

    // 1) QKV projection: [8192,1024] @ [1024,3072] + bias  (tf32 tensor cores)
    {
        dim3 grid(QKVN / 128, M / 128);
        gemm_tf32_bias_kernel<<<grid, 256>>>(x, W_attn, b_attn, qkv, M, QKVN, DIM);
    }

    // 2) Causal flash attention (fp32)
    {
        const int smem = 4 * 64 * SSTR * (int)sizeof(float);  // 69632 B
        cudaFuncSetAttribute(attn_kernel, cudaFuncAttributeMaxDynamicSharedMemorySize, smem);
        dim3 grid(SEQ / 64, NHEAD, BATCH);
        attn_kernel<<<grid, 256, smem>>>(qkv, y);
    }

    // 3) Output projection: [8192,1024] @ [1024,1024] + bias  (tf32 tensor cores)
    {
        dim3 grid(DIM / 128, M / 128);
        gemm_tf32_bias_kernel<<<grid, 256>>>(y, W_proj, b_proj, out, M, DIM, DIM);
    }
}

// round 3
// speedup vs baseline: 6.3506x; 5.9616x over previous
#include <cuda_runtime.h>
#include <cuda_bf16.h>
#include <math.h>

#define BATCH 4
#define SEQ   2048
#define DIM   1024
#define NHEAD 16
#define HDIM  64
#define QKVN  (3 * DIM)   // 3072

__device__ float g_qkv[(size_t)BATCH * SEQ * QKVN];
__device__ float g_y[(size_t)BATCH * SEQ * DIM];

__device__ __forceinline__ unsigned f2tf32(float x) {
    unsigned u;
    asm("cvt.rna.tf32.f32 %0, %1;" : "=r"(u) : "f"(x));
    return u;
}

__device__ __forceinline__ void mma_tf32(float c[4], const unsigned a[4], const unsigned b[2]) {
    asm volatile(
        "mma.sync.aligned.m16n8k8.row.col.f32.tf32.tf32.f32 "
        "{%0,%1,%2,%3}, {%4,%5,%6,%7}, {%8,%9}, {%0,%1,%2,%3};\n"
        : "+f"(c[0]), "+f"(c[1]), "+f"(c[2]), "+f"(c[3])
        : "r"(a[0]), "r"(a[1]), "r"(a[2]), "r"(a[3]),
          "r"(b[0]), "r"(b[1]));
}

// ---------------------------------------------------------------------------
// TF32 tensor-core GEMM with fused bias: C[M,N] = A[M,K] @ B[K,N] + bias[N]
// BM=BN=128, BK=32, 256 threads (8 warps 4x2), forced 2 CTAs/SM.
// ---------------------------------------------------------------------------
#define ASTR 133
#define BSTR 132

__global__ __launch_bounds__(256, 2) void gemm_tf32_bias_kernel(
    const float* __restrict__ A, const float* __restrict__ B,
    const float* __restrict__ bias, float* __restrict__ C,
    int M, int N, int K)
{
    __shared__ float As[32 * ASTR];
    __shared__ float Bs[32 * BSTR];

    const int tid  = threadIdx.x;
    const int row0 = blockIdx.y * 128;
    const int col0 = blockIdx.x * 128;

    const int wid = tid >> 5;
    const int lid = tid & 31;
    const int wm  = wid & 3;
    const int wn  = wid >> 2;
    const int g   = lid >> 2;
    const int t   = lid & 3;

    const int a_r  = tid >> 1;
    const int a_c0 = (tid & 1) * 16;
    const int b_r  = tid >> 3;
    const int b_c0 = (tid & 7) * 16;

    const float* Aptr = A + (size_t)(row0 + a_r) * K + a_c0;
    const float* Bptr = B + (size_t)b_r * N + col0 + b_c0;

    float c_[2][8][4];
#pragma unroll
    for (int mt = 0; mt < 2; mt++)
#pragma unroll
        for (int nt = 0; nt < 8; nt++)
#pragma unroll
            for (int i = 0; i < 4; i++) c_[mt][nt][i] = 0.f;

    float4 ar[4], br[4];
#pragma unroll
    for (int j = 0; j < 4; j++) {
        ar[j] = *(const float4*)(Aptr + j * 4);
        br[j] = *(const float4*)(Bptr + j * 4);
    }

    const int KITER = K / 32;
    for (int it = 0; it < KITER; it++) {
#pragma unroll
        for (int j = 0; j < 4; j++) {
            As[(a_c0 + j * 4 + 0) * ASTR + a_r] = __uint_as_float(f2tf32(ar[j].x));
            As[(a_c0 + j * 4 + 1) * ASTR + a_r] = __uint_as_float(f2tf32(ar[j].y));
            As[(a_c0 + j * 4 + 2) * ASTR + a_r] = __uint_as_float(f2tf32(ar[j].z));
            As[(a_c0 + j * 4 + 3) * ASTR + a_r] = __uint_as_float(f2tf32(ar[j].w));
            float4 bv;
            bv.x = __uint_as_float(f2tf32(br[j].x));
            bv.y = __uint_as_float(f2tf32(br[j].y));
            bv.z = __uint_as_float(f2tf32(br[j].z));
            bv.w = __uint_as_float(f2tf32(br[j].w));
            *(float4*)&Bs[b_r * BSTR + b_c0 + j * 4] = bv;
        }
        __syncthreads();

        if (it + 1 < KITER) {
            const float* An = Aptr + (it + 1) * 32;
            const float* Bn = Bptr + (size_t)(it + 1) * 32 * N;
#pragma unroll
            for (int j = 0; j < 4; j++) {
                ar[j] = *(const float4*)(An + j * 4);
                br[j] = *(const float4*)(Bn + j * 4);
            }
        }

#pragma unroll
        for (int ks = 0; ks < 4; ks++) {
            const int ko = ks * 8;
            unsigned a_[2][4], b_[8][2];
#pragma unroll
            for (int mt = 0; mt < 2; mt++) {
                const int mo = wm * 32 + mt * 16;
                a_[mt][0] = __float_as_uint(As[(ko + t)     * ASTR + mo + g]);
                a_[mt][1] = __float_as_uint(As[(ko + t)     * ASTR + mo + g + 8]);
                a_[mt][2] = __float_as_uint(As[(ko + t + 4) * ASTR + mo + g]);
                a_[mt][3] = __float_as_uint(As[(ko + t + 4) * ASTR + mo + g + 8]);
            }
#pragma unroll
            for (int nt = 0; nt < 8; nt++) {
                const int no = wn * 64 + nt * 8;
                b_[nt][0] = __float_as_uint(Bs[(ko + t)     * BSTR + no + g]);
                b_[nt][1] = __float_as_uint(Bs[(ko + t + 4) * BSTR + no + g]);
            }
#pragma unroll
            for (int mt = 0; mt < 2; mt++)
#pragma unroll
                for (int nt = 0; nt < 8; nt++)
                    mma_tf32(c_[mt][nt], a_[mt], b_[nt]);
        }
        __syncthreads();
    }

#pragma unroll
    for (int mt = 0; mt < 2; mt++) {
        const int r0 = row0 + wm * 32 + mt * 16 + g;
#pragma unroll
        for (int nt = 0; nt < 8; nt++) {
            const int c = col0 + wn * 64 + nt * 8 + 2 * t;
            const float b0 = __ldg(&bias[c]);
            const float b1 = __ldg(&bias[c + 1]);
            float2 v0, v1;
            v0.x = c_[mt][nt][0] + b0;
            v0.y = c_[mt][nt][1] + b1;
            v1.x = c_[mt][nt][2] + b0;
            v1.y = c_[mt][nt][3] + b1;
            *(float2*)&C[(size_t)r0 * N + c]       = v0;
            *(float2*)&C[(size_t)(r0 + 8) * N + c] = v1;
        }
    }
}

// ---------------------------------------------------------------------------
// TF32 tensor-core causal flash attention.
// CTA = (b, h, 128-query tile). 8 warps; warp w owns rows w*16..w*16+15.
// Bc = 64 keys per inner tile. Softmax per 4-lane quad (shuffles only).
// Strides chosen so every fragment LDS is bank-conflict-free:
//   row-indexed-by-g arrays (Q/K/P): stride 68 (== 4 mod 32 banks)
//   Vs (row indexed by t):           stride 72 (== 8 mod 32 banks)
// ---------------------------------------------------------------------------
#define QSTR 68
#define KSTR 68
#define VSTR 72
#define PSTR 68

__global__ __launch_bounds__(256, 2) void attn_mma_kernel(
    const float* __restrict__ qkv, float* __restrict__ y)
{
    extern __shared__ float sm[];
    float* Qs = sm;                       // 128 x QSTR
    float* Ks = Qs + 128 * QSTR;          // 64 x KSTR
    float* Vs = Ks + 64 * KSTR;           // 64 x VSTR
    float* Ps = Vs + 64 * VSTR;           // 128 x PSTR

    const int qt  = blockIdx.x;           // 0..15
    const int h   = blockIdx.y;
    const int b   = blockIdx.z;
    const int tid = threadIdx.x;
    const int wid = tid >> 5;
    const int lid = tid & 31;
    const int g   = lid >> 2;
    const int t   = lid & 3;
    const int q0  = qt * 128;

    const size_t base = (size_t)b * SEQ * QKVN + h * HDIM;

    // Load Q tile (128 x 64), scale by 1/8, convert to tf32
    {
        const int lr = tid >> 4;           // 0..15
        const int c4 = (tid & 15) * 4;     // 0..60
#pragma unroll
        for (int p = 0; p < 8; p++) {
            const int row = lr + p * 16;
            float4 v = *(const float4*)&qkv[base + (size_t)(q0 + row) * QKVN + c4];
            uint4 u;
            u.x = f2tf32(v.x * 0.125f);
            u.y = f2tf32(v.y * 0.125f);
            u.z = f2tf32(v.z * 0.125f);
            u.w = f2tf32(v.w * 0.125f);
            *(uint4*)&Qs[row * QSTR + c4] = u;
        }
    }

    // Row states: this lane handles rows r0 = q0 + wid*16 + g and r0+8
    float m0 = -INFINITY, m1 = -INFINITY;
    float l0 = 0.f, l1 = 0.f;
    float O[8][4];
#pragma unroll
    for (int nt = 0; nt < 8; nt++)
#pragma unroll
        for (int i = 0; i < 4; i++) O[nt][i] = 0.f;

    const int warp_row = q0 + wid * 16;   // first row owned by this warp
    const int ktiles = 2 * qt + 2;

    for (int kt = 0; kt < ktiles; kt++) {
        const int k0 = kt * 64;
        __syncthreads();   // prior QK/PV reads of Ks/Vs complete

        // Load K and V tiles (64 x 64 each), convert to tf32
        {
            const int lr = tid >> 4;
            const int c4 = (tid & 15) * 4;
#pragma unroll
            for (int p = 0; p < 4; p++) {
                const int row = lr + p * 16;
                const size_t gbase = base + (size_t)(k0 + row) * QKVN + c4;
                float4 kv = *(const float4*)&qkv[gbase + DIM];
                float4 vv = *(const float4*)&qkv[gbase + 2 * DIM];
                uint4 ku, vu;
                ku.x = f2tf32(kv.x); ku.y = f2tf32(kv.y);
                ku.z = f2tf32(kv.z); ku.w = f2tf32(kv.w);
                vu.x = f2tf32(vv.x); vu.y = f2tf32(vv.y);
                vu.z = f2tf32(vv.z); vu.w = f2tf32(vv.w);
                *(uint4*)&Ks[row * KSTR + c4] = ku;
                *(uint4*)&Vs[row * VSTR + c4] = vu;
            }
        }
        __syncthreads();

        // Warps entirely above this key tile have nothing to do
        if (k0 <= warp_row + 15) {
            // ---- S = Q K^T for rows warp_row..+15, cols k0..k0+63 ----
            float s[8][4];
#pragma unroll
            for (int nt = 0; nt < 8; nt++)
#pragma unroll
                for (int i = 0; i < 4; i++) s[nt][i] = 0.f;

#pragma unroll
            for (int ks = 0; ks < 8; ks++) {
                const int ko = ks * 8;
                unsigned a_[4], b_[2];
                a_[0] = __float_as_uint(Qs[(wid * 16 + g)     * QSTR + ko + t]);
                a_[1] = __float_as_uint(Qs[(wid * 16 + g + 8) * QSTR + ko + t]);
                a_[2] = __float_as_uint(Qs[(wid * 16 + g)     * QSTR + ko + t + 4]);
                a_[3] = __float_as_uint(Qs[(wid * 16 + g + 8) * QSTR + ko + t + 4]);
#pragma unroll
                for (int nt = 0; nt < 8; nt++) {
                    b_[0] = __float_as_uint(Ks[(nt * 8 + g) * KSTR + ko + t]);
                    b_[1] = __float_as_uint(Ks[(nt * 8 + g) * KSTR + ko + t + 4]);
                    mma_tf32(s[nt], a_, b_);
                }
            }

            // ---- causal mask (only when tile crosses the diagonal) ----
            const int r0g = warp_row + g;
            if (k0 + 63 > r0g) {
#pragma unroll
                for (int nt = 0; nt < 8; nt++) {
                    const int c0 = k0 + nt * 8 + 2 * t;
                    if (c0     > r0g)     s[nt][0] = -INFINITY;
                    if (c0 + 1 > r0g)     s[nt][1] = -INFINITY;
                    if (c0     > r0g + 8) s[nt][2] = -INFINITY;
                    if (c0 + 1 > r0g + 8) s[nt][3] = -INFINITY;
                }
            }

            // ---- online softmax (row g in c0/c1, row g+8 in c2/c3) ----
            float mt0 = -INFINITY, mt1 = -INFINITY;
#pragma unroll
            for (int nt = 0; nt < 8; nt++) {
                mt0 = fmaxf(mt0, fmaxf(s[nt][0], s[nt][1]));
                mt1 = fmaxf(mt1, fmaxf(s[nt][2], s[nt][3]));
            }
            mt0 = fmaxf(mt0, __shfl_xor_sync(0xffffffffu, mt0, 1));
            mt0 = fmaxf(mt0, __shfl_xor_sync(0xffffffffu, mt0, 2));
            mt1 = fmaxf(mt1, __shfl_xor_sync(0xffffffffu, mt1, 1));
            mt1 = fmaxf(mt1, __shfl_xor_sync(0xffffffffu, mt1, 2));

            const float m0n = fmaxf(m0, mt0);
            const float m1n = fmaxf(m1, mt1);
            const float c0f = __expf(m0 - m0n);
            const float c1f = __expf(m1 - m1n);

            float sum0 = 0.f, sum1 = 0.f;
#pragma unroll
            for (int nt = 0; nt < 8; nt++) {
                const float p0 = __expf(s[nt][0] - m0n);
                const float p1 = __expf(s[nt][1] - m0n);
                const float p2 = __expf(s[nt][2] - m1n);
                const float p3 = __expf(s[nt][3] - m1n);
                sum0 += p0 + p1;
                sum1 += p2 + p3;
                // store P fragments (tf32) to smem: row g at cols nt*8+2t, row g+8 same cols
                float2 w0, w1;
                w0.x = __uint_as_float(f2tf32(p0));
                w0.y = __uint_as_float(f2tf32(p1));
                w1.x = __uint_as_float(f2tf32(p2));
                w1.y = __uint_as_float(f2tf32(p3));
                *(float2*)&Ps[(wid * 16 + g)     * PSTR + nt * 8 + 2 * t] = w0;
                *(float2*)&Ps[(wid * 16 + g + 8) * PSTR + nt * 8 + 2 * t] = w1;
            }
            sum0 += __shfl_xor_sync(0xffffffffu, sum0, 1);
            sum0 += __shfl_xor_sync(0xffffffffu, sum0, 2);
            sum1 += __shfl_xor_sync(0xffffffffu, sum1, 1);
            sum1 += __shfl_xor_sync(0xffffffffu, sum1, 2);

            l0 = l0 * c0f + sum0;
            l1 = l1 * c1f + sum1;
            m0 = m0n;
            m1 = m1n;
#pragma unroll
            for (int nt = 0; nt < 8; nt++) {
                O[nt][0] *= c0f; O[nt][1] *= c0f;
                O[nt][2] *= c1f; O[nt][3] *= c1f;
            }

            __syncwarp();  // P visible within warp

            // ---- O += P @ V  (k = 64 keys, n = 64 head dims) ----
#pragma unroll
            for (int ks = 0; ks < 8; ks++) {
                const int ko = ks * 8;
                unsigned a_[4], b_[2];
                a_[0] = __float_as_uint(Ps[(wid * 16 + g)     * PSTR + ko + t]);
                a_[1] = __float_as_uint(Ps[(wid * 16 + g + 8) * PSTR + ko + t]);
                a_[2] = __float_as_uint(Ps[(wid * 16 + g)     * PSTR + ko + t + 4]);
                a_[3] = __float_as_uint(Ps[(wid * 16 + g + 8) * PSTR + ko + t + 4]);
#pragma unroll
                for (int nt = 0; nt < 8; nt++) {
                    b_[0] = __float_as_uint(Vs[(ko + t)     * VSTR + nt * 8 + g]);
                    b_[1] = __float_as_uint(Vs[(ko + t + 4) * VSTR + nt * 8 + g]);
                    mma_tf32(O[nt], a_, b_);
                }
            }
        }
    }

    // ---- normalize and store y rows ----
    const float inv0 = 1.f / l0;
    const float inv1 = 1.f / l1;
    const int r0 = q0 + wid * 16 + g;
    const size_t y0 = ((size_t)b * SEQ + r0) * DIM + h * HDIM;
    const size_t y1 = y0 + 8 * DIM;
#pragma unroll
    for (int nt = 0; nt < 8; nt++) {
        const int c = nt * 8 + 2 * t;
        float2 o0, o1;
        o0.x = O[nt][0] * inv0; o0.y = O[nt][1] * inv0;
        o1.x = O[nt][2] * inv1; o1.y = O[nt][3] * inv1;
        *(float2*)&y[y0 + c] = o0;
        *(float2*)&y[y1 + c] = o1;
    }
}

// ---------------------------------------------------------------------------
// Launch
// ---------------------------------------------------------------------------
extern "C" void kernel_launch(void* const* d_in, const int* in_sizes, int n_in,
                              void* d_out, int out_size)
{
    const float* x      = (const float*)d_in[0];
    const float* W_attn = (const float*)d_in[1];
    const float* b_attn = (const float*)d_in[2];
    const float* W_proj = (const float*)d_in[3];
    const float* b_proj = (const float*)d_in[4];
    float* out = (float*)d_out;

    void* qkv_p = nullptr;
    void* y_p   = nullptr;
    cudaGetSymbolAddress(&qkv_p, g_qkv);
    cudaGetSymbolAddress(&y_p, g_y);
    float* qkv = (float*)qkv_p;
    float* y   = (float*)y_p;

    const int M = BATCH * SEQ;  // 8192

    // 1) QKV projection (tf32 tensor cores)
    {
        dim3 grid(QKVN / 128, M / 128);
        gemm_tf32_bias_kernel<<<grid, 256>>>(x, W_attn, b_attn, qkv, M, QKVN, DIM);
    }

    // 2) Causal flash attention (tf32 tensor cores)
    {
        const int smem = (128 * QSTR + 64 * KSTR + 64 * VSTR + 128 * PSTR) * (int)sizeof(float);
        cudaFuncSetAttribute(attn_mma_kernel, cudaFuncAttributeMaxDynamicSharedMemorySize, smem);
        dim3 grid(SEQ / 128, NHEAD, BATCH);
        attn_mma_kernel<<<grid, 256, smem>>>(qkv, y);
    }

    // 3) Output projection (tf32 tensor cores)
    {
        dim3 grid(DIM / 128, M / 128);
        gemm_tf32_bias_kernel<<<grid, 256>>>(y, W_proj, b_proj, out, M, DIM, DIM);
    }
}

// round 9
// speedup vs baseline: 9.3831x; 1.4775x over previous
#include <cuda_runtime.h>
#include <cuda_bf16.h>
#include <math.h>
#include <cstdint>

#define BATCH 4
#define SEQ   2048
#define DIM   1024
#define NHEAD 16
#define HDIM  64
#define QKVN  (3 * DIM)   // 3072

__device__ float g_qkv[(size_t)BATCH * SEQ * QKVN];
__device__ float g_y[(size_t)BATCH * SEQ * DIM];

// ===========================================================================
// Common helpers
// ===========================================================================
__device__ __forceinline__ unsigned f2tf32(float x) {
    unsigned u;
    asm("cvt.rna.tf32.f32 %0, %1;" : "=r"(u) : "f"(x));
    return u;
}

__device__ __forceinline__ void mma_tf32(float c[4], const unsigned a[4], const unsigned b[2]) {
    asm volatile(
        "mma.sync.aligned.m16n8k8.row.col.f32.tf32.tf32.f32 "
        "{%0,%1,%2,%3}, {%4,%5,%6,%7}, {%8,%9}, {%0,%1,%2,%3};\n"
        : "+f"(c[0]), "+f"(c[1]), "+f"(c[2]), "+f"(c[3])
        : "r"(a[0]), "r"(a[1]), "r"(a[2]), "r"(a[3]),
          "r"(b[0]), "r"(b[1]));
}

__device__ __forceinline__ uint32_t smem_u32(const void* p) {
    uint32_t a;
    asm("{ .reg .u64 t; cvta.to.shared.u64 t, %1; cvt.u32.u64 %0, t; }"
        : "=r"(a) : "l"(p));
    return a;
}

__device__ __forceinline__ void cpa16(uint32_t dst, const void* src) {
    asm volatile("cp.async.cg.shared.global [%0], [%1], 16;\n"
                 :: "r"(dst), "l"(src) : "memory");
}

// ===========================================================================
// TF32 mma.sync GEMM v2: C[M,N] = A[M,K] @ B[K,N] + bias[N]
// CTA 128x128, BK=32, 128 threads = 4 warps (2x2 grid of 64x64 warp tiles).
// cp.async double-buffered smem (raw fp32); cvt->tf32 at fragment load.
// Conflict-free fragment strides: A m-major stride 36 (==4 mod 32),
// B k-major stride 136 (==8 mod 32).
// ===========================================================================
#define AST2 36                      // floats per A smem row (32 data + 4 pad)
#define BST2 136                     // floats per B smem row (128 data + 8 pad)
#define A_STAGE (128 * AST2)         // 4608 floats = 18432 B
#define B_STAGE (32 * BST2)          // 4352 floats = 17408 B
#define GSMEM_BYTES ((2 * A_STAGE + 2 * B_STAGE) * 4)   // 71680 B

__global__ __launch_bounds__(128) void gemm_mma_kernel(
    const float* __restrict__ A, const float* __restrict__ Bw,
    const float* __restrict__ bias, float* __restrict__ C,
    int N, int K)
{
    extern __shared__ float smem[];
    float* sA = smem;                     // 2 stages of A
    float* sB = smem + 2 * A_STAGE;       // 2 stages of B
    const uint32_t sAu = smem_u32(sA);
    const uint32_t sBu = smem_u32(sB);

    const int tid  = threadIdx.x;
    const int wid  = tid >> 5;
    const int lid  = tid & 31;
    const int wm   = wid & 1;             // m offset wm*64
    const int wn   = wid >> 1;            // n offset wn*64
    const int g    = lid >> 2;            // 0..7
    const int t    = lid & 3;             // 0..3
    const int row0 = blockIdx.y * 128;
    const int col0 = blockIdx.x * 128;

    float acc[4][8][4];
#pragma unroll
    for (int mt = 0; mt < 4; mt++)
#pragma unroll
        for (int nt = 0; nt < 8; nt++)
#pragma unroll
            for (int i = 0; i < 4; i++) acc[mt][nt][i] = 0.f;

    const int NIT = K / 32;

    // ---- stage loader: A 128x32 (m-major rows), B 32x128 (k-major rows) ----
    // A tile: 128 rows x 32 floats = 1024 16B-chunks (8 chunks/row)
    // B tile:  32 rows x 128 floats = 1024 16B-chunks (32 chunks/row)
    auto load_stage = [&](int it, int st) {
        const int k0 = it * 32;
        const uint32_t aBase = sAu + (uint32_t)st * A_STAGE * 4;
        const uint32_t bBase = sBu + (uint32_t)st * B_STAGE * 4;
#pragma unroll
        for (int i = 0; i < 8; i++) {          // A: 1024 chunks / 128 thr
            const int c  = tid + i * 128;
            const int m  = c >> 3;             // 0..127
            const int ch = c & 7;              // 0..7 -> k float offset ch*4
            cpa16(aBase + (uint32_t)(m * AST2 + ch * 4) * 4,
                  &A[(size_t)(row0 + m) * K + k0 + ch * 4]);
        }
#pragma unroll
        for (int i = 0; i < 8; i++) {          // B: 1024 chunks / 128 thr
            const int c  = tid + i * 128;
            const int r  = c >> 5;             // 0..31 (k row)
            const int ch = c & 31;             // 0..31 -> n float offset ch*4
            cpa16(bBase + (uint32_t)(r * BST2 + ch * 4) * 4,
                  &Bw[(size_t)(k0 + r) * N + col0 + ch * 4]);
        }
        asm volatile("cp.async.commit_group;\n" ::: "memory");
    };

    load_stage(0, 0);

    for (int it = 0; it < NIT; it++) {
        if (it + 1 < NIT) {
            load_stage(it + 1, (it + 1) & 1);
            asm volatile("cp.async.wait_group 1;\n" ::: "memory");
        } else {
            asm volatile("cp.async.wait_group 0;\n" ::: "memory");
        }
        __syncthreads();

        const float* As_ = sA + (it & 1) * A_STAGE;
        const float* Bs_ = sB + (it & 1) * B_STAGE;

#pragma unroll
        for (int ks = 0; ks < 4; ks++) {
            const int ko = ks * 8;
            unsigned a_[4][4];
#pragma unroll
            for (int mt = 0; mt < 4; mt++) {
                const int mo = wm * 64 + mt * 16;
                a_[mt][0] = f2tf32(As_[(mo + g)     * AST2 + ko + t]);
                a_[mt][1] = f2tf32(As_[(mo + g + 8) * AST2 + ko + t]);
                a_[mt][2] = f2tf32(As_[(mo + g)     * AST2 + ko + t + 4]);
                a_[mt][3] = f2tf32(As_[(mo + g + 8) * AST2 + ko + t + 4]);
            }
            unsigned b_[8][2];
#pragma unroll
            for (int nt = 0; nt < 8; nt++) {
                const int no = wn * 64 + nt * 8;
                b_[nt][0] = f2tf32(Bs_[(ko + t)     * BST2 + no + g]);
                b_[nt][1] = f2tf32(Bs_[(ko + t + 4) * BST2 + no + g]);
            }
#pragma unroll
            for (int mt = 0; mt < 4; mt++)
#pragma unroll
                for (int nt = 0; nt < 8; nt++)
                    mma_tf32(acc[mt][nt], a_[mt], b_[nt]);
        }
        __syncthreads();
    }

    // ---- epilogue: bias + float2 stores ----
#pragma unroll
    for (int mt = 0; mt < 4; mt++) {
        const int r0 = row0 + wm * 64 + mt * 16 + g;
#pragma unroll
        for (int nt = 0; nt < 8; nt++) {
            const int c = col0 + wn * 64 + nt * 8 + 2 * t;
            const float b0 = __ldg(&bias[c]);
            const float b1 = __ldg(&bias[c + 1]);
            float2 v0, v1;
            v0.x = acc[mt][nt][0] + b0;
            v0.y = acc[mt][nt][1] + b1;
            v1.x = acc[mt][nt][2] + b0;
            v1.y = acc[mt][nt][3] + b1;
            *(float2*)&C[(size_t)r0 * N + c]       = v0;
            *(float2*)&C[(size_t)(r0 + 8) * N + c] = v1;
        }
    }
}

// ===========================================================================
// TF32 mma.sync causal flash attention (unchanged — passing at ~375us)
// ===========================================================================
#define QSTR 68
#define KSTR 68
#define VSTR 72
#define PSTR 68

__global__ __launch_bounds__(256, 2) void attn_mma_kernel(
    const float* __restrict__ qkv, float* __restrict__ y)
{
    extern __shared__ float sm[];
    float* Qs = sm;
    float* Ks = Qs + 128 * QSTR;
    float* Vs = Ks + 64 * KSTR;
    float* Ps = Vs + 64 * VSTR;

    const int qt  = blockIdx.x;
    const int h   = blockIdx.y;
    const int b   = blockIdx.z;
    const int tid = threadIdx.x;
    const int wid = tid >> 5;
    const int lid = tid & 31;
    const int g   = lid >> 2;
    const int t   = lid & 3;
    const int q0  = qt * 128;

    const size_t base = (size_t)b * SEQ * QKVN + h * HDIM;

    {
        const int lr = tid >> 4;
        const int c4 = (tid & 15) * 4;
#pragma unroll
        for (int p = 0; p < 8; p++) {
            const int row = lr + p * 16;
            float4 v = *(const float4*)&qkv[base + (size_t)(q0 + row) * QKVN + c4];
            uint4 u;
            u.x = f2tf32(v.x * 0.125f);
            u.y = f2tf32(v.y * 0.125f);
            u.z = f2tf32(v.z * 0.125f);
            u.w = f2tf32(v.w * 0.125f);
            *(uint4*)&Qs[row * QSTR + c4] = u;
        }
    }

    float m0 = -INFINITY, m1 = -INFINITY;
    float l0 = 0.f, l1 = 0.f;
    float O[8][4];
#pragma unroll
    for (int nt = 0; nt < 8; nt++)
#pragma unroll
        for (int i = 0; i < 4; i++) O[nt][i] = 0.f;

    const int warp_row = q0 + wid * 16;
    const int ktiles = 2 * qt + 2;

    for (int kt = 0; kt < ktiles; kt++) {
        const int k0 = kt * 64;
        __syncthreads();

        {
            const int lr = tid >> 4;
            const int c4 = (tid & 15) * 4;
#pragma unroll
            for (int p = 0; p < 4; p++) {
                const int row = lr + p * 16;
                const size_t gbase = base + (size_t)(k0 + row) * QKVN + c4;
                float4 kv = *(const float4*)&qkv[gbase + DIM];
                float4 vv = *(const float4*)&qkv[gbase + 2 * DIM];
                uint4 ku, vu;
                ku.x = f2tf32(kv.x); ku.y = f2tf32(kv.y);
                ku.z = f2tf32(kv.z); ku.w = f2tf32(kv.w);
                vu.x = f2tf32(vv.x); vu.y = f2tf32(vv.y);
                vu.z = f2tf32(vv.z); vu.w = f2tf32(vv.w);
                *(uint4*)&Ks[row * KSTR + c4] = ku;
                *(uint4*)&Vs[row * VSTR + c4] = vu;
            }
        }
        __syncthreads();

        if (k0 <= warp_row + 15) {
            float s[8][4];
#pragma unroll
            for (int nt = 0; nt < 8; nt++)
#pragma unroll
                for (int i = 0; i < 4; i++) s[nt][i] = 0.f;

#pragma unroll
            for (int ks = 0; ks < 8; ks++) {
                const int ko = ks * 8;
                unsigned a_[4], b_[2];
                a_[0] = __float_as_uint(Qs[(wid * 16 + g)     * QSTR + ko + t]);
                a_[1] = __float_as_uint(Qs[(wid * 16 + g + 8) * QSTR + ko + t]);
                a_[2] = __float_as_uint(Qs[(wid * 16 + g)     * QSTR + ko + t + 4]);
                a_[3] = __float_as_uint(Qs[(wid * 16 + g + 8) * QSTR + ko + t + 4]);
#pragma unroll
                for (int nt = 0; nt < 8; nt++) {
                    b_[0] = __float_as_uint(Ks[(nt * 8 + g) * KSTR + ko + t]);
                    b_[1] = __float_as_uint(Ks[(nt * 8 + g) * KSTR + ko + t + 4]);
                    mma_tf32(s[nt], a_, b_);
                }
            }

            const int r0g = warp_row + g;
            if (k0 + 63 > r0g) {
#pragma unroll
                for (int nt = 0; nt < 8; nt++) {
                    const int c0 = k0 + nt * 8 + 2 * t;
                    if (c0     > r0g)     s[nt][0] = -INFINITY;
                    if (c0 + 1 > r0g)     s[nt][1] = -INFINITY;
                    if (c0     > r0g + 8) s[nt][2] = -INFINITY;
                    if (c0 + 1 > r0g + 8) s[nt][3] = -INFINITY;
                }
            }

            float mt0 = -INFINITY, mt1 = -INFINITY;
#pragma unroll
            for (int nt = 0; nt < 8; nt++) {
                mt0 = fmaxf(mt0, fmaxf(s[nt][0], s[nt][1]));
                mt1 = fmaxf(mt1, fmaxf(s[nt][2], s[nt][3]));
            }
            mt0 = fmaxf(mt0, __shfl_xor_sync(0xffffffffu, mt0, 1));
            mt0 = fmaxf(mt0, __shfl_xor_sync(0xffffffffu, mt0, 2));
            mt1 = fmaxf(mt1, __shfl_xor_sync(0xffffffffu, mt1, 1));
            mt1 = fmaxf(mt1, __shfl_xor_sync(0xffffffffu, mt1, 2));

            const float m0n = fmaxf(m0, mt0);
            const float m1n = fmaxf(m1, mt1);
            const float c0f = __expf(m0 - m0n);
            const float c1f = __expf(m1 - m1n);

            float sum0 = 0.f, sum1 = 0.f;
#pragma unroll
            for (int nt = 0; nt < 8; nt++) {
                const float p0 = __expf(s[nt][0] - m0n);
                const float p1 = __expf(s[nt][1] - m0n);
                const float p2 = __expf(s[nt][2] - m1n);
                const float p3 = __expf(s[nt][3] - m1n);
                sum0 += p0 + p1;
                sum1 += p2 + p3;
                float2 w0, w1;
                w0.x = __uint_as_float(f2tf32(p0));
                w0.y = __uint_as_float(f2tf32(p1));
                w1.x = __uint_as_float(f2tf32(p2));
                w1.y = __uint_as_float(f2tf32(p3));
                *(float2*)&Ps[(wid * 16 + g)     * PSTR + nt * 8 + 2 * t] = w0;
                *(float2*)&Ps[(wid * 16 + g + 8) * PSTR + nt * 8 + 2 * t] = w1;
            }
            sum0 += __shfl_xor_sync(0xffffffffu, sum0, 1);
            sum0 += __shfl_xor_sync(0xffffffffu, sum0, 2);
            sum1 += __shfl_xor_sync(0xffffffffu, sum1, 1);
            sum1 += __shfl_xor_sync(0xffffffffu, sum1, 2);

            l0 = l0 * c0f + sum0;
            l1 = l1 * c1f + sum1;
            m0 = m0n;
            m1 = m1n;
#pragma unroll
            for (int nt = 0; nt < 8; nt++) {
                O[nt][0] *= c0f; O[nt][1] *= c0f;
                O[nt][2] *= c1f; O[nt][3] *= c1f;
            }

            __syncwarp();

#pragma unroll
            for (int ks = 0; ks < 8; ks++) {
                const int ko = ks * 8;
                unsigned a_[4], b_[2];
                a_[0] = __float_as_uint(Ps[(wid * 16 + g)     * PSTR + ko + t]);
                a_[1] = __float_as_uint(Ps[(wid * 16 + g + 8) * PSTR + ko + t]);
                a_[2] = __float_as_uint(Ps[(wid * 16 + g)     * PSTR + ko + t + 4]);
                a_[3] = __float_as_uint(Ps[(wid * 16 + g + 8) * PSTR + ko + t + 4]);
#pragma unroll
                for (int nt = 0; nt < 8; nt++) {
                    b_[0] = __float_as_uint(Vs[(ko + t)     * VSTR + nt * 8 + g]);
                    b_[1] = __float_as_uint(Vs[(ko + t + 4) * VSTR + nt * 8 + g]);
                    mma_tf32(O[nt], a_, b_);
                }
            }
        }
    }

    const float inv0 = 1.f / l0;
    const float inv1 = 1.f / l1;
    const int r0 = q0 + wid * 16 + g;
    const size_t y0 = ((size_t)b * SEQ + r0) * DIM + h * HDIM;
    const size_t y1 = y0 + 8 * DIM;
#pragma unroll
    for (int nt = 0; nt < 8; nt++) {
        const int c = nt * 8 + 2 * t;
        float2 o0, o1;
        o0.x = O[nt][0] * inv0; o0.y = O[nt][1] * inv0;
        o1.x = O[nt][2] * inv1; o1.y = O[nt][3] * inv1;
        *(float2*)&y[y0 + c] = o0;
        *(float2*)&y[y1 + c] = o1;
    }
}

// ===========================================================================
// Launch
// ===========================================================================
extern "C" void kernel_launch(void* const* d_in, const int* in_sizes, int n_in,
                              void* d_out, int out_size)
{
    const float* x      = (const float*)d_in[0];
    const float* W_attn = (const float*)d_in[1];
    const float* b_attn = (const float*)d_in[2];
    const float* W_proj = (const float*)d_in[3];
    const float* b_proj = (const float*)d_in[4];
    float* out = (float*)d_out;

    void* qkv_p = nullptr;
    void* y_p   = nullptr;
    cudaGetSymbolAddress(&qkv_p, g_qkv);
    cudaGetSymbolAddress(&y_p, g_y);
    float* qkv = (float*)qkv_p;
    float* y   = (float*)y_p;

    const int M = BATCH * SEQ;  // 8192

    cudaFuncSetAttribute(gemm_mma_kernel,
                         cudaFuncAttributeMaxDynamicSharedMemorySize, GSMEM_BYTES);

    // 1) QKV projection: [8192,1024] @ [1024,3072] + bias
    {
        dim3 grid(QKVN / 128, M / 128);
        gemm_mma_kernel<<<grid, 128, GSMEM_BYTES>>>(x, W_attn, b_attn, qkv, QKVN, DIM);
    }

    // 2) Causal flash attention (tf32 mma.sync)
    {
        const int smem = (128 * QSTR + 64 * KSTR + 64 * VSTR + 128 * PSTR) * (int)sizeof(float);
        cudaFuncSetAttribute(attn_mma_kernel, cudaFuncAttributeMaxDynamicSharedMemorySize, smem);
        dim3 grid(SEQ / 128, NHEAD, BATCH);
        attn_mma_kernel<<<grid, 256, smem>>>(qkv, y);
    }

    // 3) Output projection: [8192,1024] @ [1024,1024] + bias
    {
        dim3 grid(DIM / 128, M / 128);
        gemm_mma_kernel<<<grid, 128, GSMEM_BYTES>>>(y, W_proj, b_proj, out, DIM, DIM);
    }
}